// round 9
// baseline (speedup 1.0000x reference)
#include <cuda_runtime.h>
#include <cstdint>

// Problem dims
#define BB   128
#define TT   256
#define HH   512
#define GG   2048
#define INN  1662
#define HD2  1024
#define NC   100
#define BT   32768

// ---------------- device scratch ----------------
__device__ float g_xpf[BT * GG];
__device__ float g_xpb[BT * GG];
__device__ float g_h0buf[BT * HD2];       // layer0 h (tf32-rounded)
__device__ float g_outbuf[BT * HD2];      // lstm_out fp32
__device__ float g_lor[BT * HD2];         // lstm_out tf32-rounded
__device__ float g_awt[HD2 * HD2];
__device__ float g_xr[BT * INN];
__device__ float g_w0f[GG * INN];
__device__ float g_w0b[GG * INN];
__device__ float g_w1f[GG * HD2];
__device__ float g_w1b[GG * HD2];
__device__ float g_hping[4 * BB * HH];
__device__ float g_scoresb[BT];
__device__ float g_attwb[BT];
__device__ float g_ctx[BB * HD2];
__device__ float g_hc[BB * HH];

__device__ unsigned g_bcnt2[2] = {0, 0};
__device__ unsigned g_bgen2[2] = {0, 0};

__device__ __forceinline__ uint32_t f2tf32(float x) {
    uint32_t u;
    asm("cvt.rna.tf32.f32 %0, %1;" : "=r"(u) : "f"(x));
    return u;
}

__device__ __forceinline__ void mma_tf32(float* d, const uint32_t* a, const uint32_t* b) {
    asm volatile(
        "mma.sync.aligned.m16n8k8.row.col.f32.tf32.tf32.f32 "
        "{%0,%1,%2,%3}, {%4,%5,%6,%7}, {%8,%9}, {%0,%1,%2,%3};"
        : "+f"(d[0]), "+f"(d[1]), "+f"(d[2]), "+f"(d[3])
        : "r"(a[0]), "r"(a[1]), "r"(a[2]), "r"(a[3]), "r"(b[0]), "r"(b[1]));
}

#define LDSM4(r0, r1, r2, r3, addr) \
    asm volatile("ldmatrix.sync.aligned.m8n8.x4.shared.b16 {%0,%1,%2,%3}, [%4];" \
        : "=r"(r0), "=r"(r1), "=r"(r2), "=r"(r3) : "r"(addr))

__device__ __forceinline__ uint32_t smem_u32(const void* p) {
    uint32_t a;
    asm("{ .reg .u64 t; cvta.to.shared.u64 t, %1; cvt.u32.u64 %0, t; }" : "=r"(a) : "l"(p));
    return a;
}
__device__ __forceinline__ void cp_async16(uint32_t dst, const void* src, int src_bytes) {
    asm volatile("cp.async.cg.shared.global [%0], [%1], 16, %2;"
                 :: "r"(dst), "l"(src), "r"(src_bytes) : "memory");
}
__device__ __forceinline__ void cp_async8(uint32_t dst, const void* src, int src_bytes) {
    asm volatile("cp.async.ca.shared.global [%0], [%1], 8, %2;"
                 :: "r"(dst), "l"(src), "r"(src_bytes) : "memory");
}
__device__ __forceinline__ void cp_commit() {
    asm volatile("cp.async.commit_group;" ::: "memory");
}
__device__ __forceinline__ void cp_wait0() {
    asm volatile("cp.async.wait_group 0;" ::: "memory");
}

// ---------------- rounding pass ----------------
__global__ void round_k(const float4* __restrict__ src, float4* __restrict__ dst, int n4)
{
    int stride = gridDim.x * blockDim.x;
    for (int i = blockIdx.x * blockDim.x + threadIdx.x; i < n4; i += stride) {
        float4 v = src[i];
        v.x = __uint_as_float(f2tf32(v.x));
        v.y = __uint_as_float(f2tf32(v.y));
        v.z = __uint_as_float(f2tf32(v.z));
        v.w = __uint_as_float(f2tf32(v.w));
        dst[i] = v;
    }
}

// ---------------- tf32 GEMM: chunk16, 2 CTA/SM, ldmatrix fragments ----------------
// Inputs pre-rounded to tf32. C[M,N] = act(A * W^T + bias). Block 128x128, 8 warps 2x4.
#define SSTR 20                           // 16 cols + 4 pad (floats); row = 80B
#define GSMEM (2 * 2 * 128 * SSTR * 4)    // 40 KB

template<int FLIP, int ACT>
__global__ __launch_bounds__(256, 2)
void gemm_mma(const float* __restrict__ A, const float* __restrict__ W,
              const float* __restrict__ bias, float* __restrict__ C,
              int M, int N, int K)
{
    extern __shared__ float dsm[];
    float* sA = dsm;                        // [2][128*SSTR]
    float* sB = dsm + 2 * 128 * SSTR;

    const int tid  = threadIdx.x;
    const int wid  = tid >> 5;
    const int lane = tid & 31;
    const int wm   = wid & 1;
    const int wn   = wid >> 1;
    const int m0 = blockIdx.y * 128;
    const int n0 = blockIdx.x * 128;
    const int lq = lane >> 2;
    const int lr = lane & 3;
    const int g  = lane >> 3;
    const int r8 = lane & 7;

    const uint32_t sA_base = smem_u32(sA);
    const uint32_t sB_base = smem_u32(sB);
    const bool use16 = ((K & 3) == 0);

    // ldmatrix per-thread row offsets (bytes)
    const uint32_t aRowOff = (uint32_t)((wm * 64 + r8 + ((g & 1) << 3)) * SSTR) * 4 + ((g >> 1) << 4);
    const uint32_t bRowOff = (uint32_t)((wn * 32 + ((g >> 1) << 3) + r8) * SSTR) * 4 + ((g & 1) << 4);

    float acc[4][4][4];
#pragma unroll
    for (int i = 0; i < 4; i++)
#pragma unroll
        for (int j = 0; j < 4; j++)
#pragma unroll
            for (int r = 0; r < 4; r++) acc[i][j][r] = 0.f;

    const int nk = (K + 15) / 16;

    auto arow_of = [&](int r) {
        int gm = m0 + r;
        if (FLIP) { int bI = gm >> 8; int t = gm & 255; return (bI << 8) + (255 - t); }
        return gm;
    };

    auto load_chunk16 = [&](int kc, int buf) {
        const int k0 = kc * 16;
        const uint32_t boff = (uint32_t)buf * 128 * SSTR * 4;
#pragma unroll
        for (int i = 0; i < 2; i++) {
            int s  = tid + i * 256;
            int r  = s >> 2;
            int c4 = s & 3;
            int k  = k0 + c4 * 4;
            int nbf = K - k; nbf = nbf < 0 ? 0 : (nbf > 4 ? 4 : nbf);
            int bytes = nbf * 4;
            int ksrc = (k < K) ? k : 0;
            uint32_t soff = (uint32_t)(r * SSTR + c4 * 4) * 4;
            cp_async16(sA_base + boff + soff, A + (size_t)arow_of(r) * K + ksrc, bytes);
            cp_async16(sB_base + boff + soff, W + (size_t)(n0 + r) * K + ksrc, bytes);
        }
        cp_commit();
    };

    auto load_chunk8 = [&](int kc, int buf) {
        const int k0 = kc * 16;
        const uint32_t boff = (uint32_t)buf * 128 * SSTR * 4;
#pragma unroll
        for (int i = 0; i < 4; i++) {
            int s  = tid + i * 256;
            int r  = s >> 3;
            int c2 = s & 7;
            int k  = k0 + c2 * 2;
            int nbf = K - k; nbf = nbf < 0 ? 0 : (nbf > 2 ? 2 : nbf);
            int bytes = nbf * 4;
            int ksrc = (k < K) ? k : 0;
            uint32_t soff = (uint32_t)(r * SSTR + c2 * 2) * 4;
            cp_async8(sA_base + boff + soff, A + (size_t)arow_of(r) * K + ksrc, bytes);
            cp_async8(sB_base + boff + soff, W + (size_t)(n0 + r) * K + ksrc, bytes);
        }
        cp_commit();
    };

    auto load_chunk = [&](int kc, int buf) {
        if (use16) load_chunk16(kc, buf); else load_chunk8(kc, buf);
    };

    load_chunk(0, 0);

    for (int kc = 0; kc < nk; kc++) {
        cp_wait0();
        __syncthreads();
        if (kc + 1 < nk) load_chunk(kc + 1, (kc + 1) & 1);

        const uint32_t bufoff = (uint32_t)(kc & 1) * 128 * SSTR * 4;
        const uint32_t bA = sA_base + bufoff;
        const uint32_t bB = sB_base + bufoff;
#pragma unroll
        for (int ks = 0; ks < 2; ks++) {
            uint32_t af[4][4];
#pragma unroll
            for (int mt = 0; mt < 4; mt++) {
                LDSM4(af[mt][0], af[mt][1], af[mt][2], af[mt][3],
                      bA + aRowOff + (uint32_t)(mt * 16 * SSTR) * 4 + ks * 32);
            }
            uint32_t bf[4][2];
#pragma unroll
            for (int p = 0; p < 2; p++) {
                uint32_t r0, r1, r2, r3;
                LDSM4(r0, r1, r2, r3,
                      bB + bRowOff + (uint32_t)(p * 16 * SSTR) * 4 + ks * 32);
                bf[2 * p][0] = r0;     bf[2 * p][1] = r1;
                bf[2 * p + 1][0] = r2; bf[2 * p + 1][1] = r3;
            }
#pragma unroll
            for (int mt = 0; mt < 4; mt++)
#pragma unroll
                for (int nt = 0; nt < 4; nt++)
                    mma_tf32(acc[mt][nt], af[mt], bf[nt]);
        }
        __syncthreads();
    }

    const int rbase = m0 + wm * 64;
    const int cbase = n0 + wn * 32;
#pragma unroll
    for (int mt = 0; mt < 4; mt++) {
#pragma unroll
        for (int nt = 0; nt < 4; nt++) {
            int c  = cbase + nt * 8 + lr * 2;
            float b0v = bias[c], b1v = bias[c + 1];
            int r0 = rbase + mt * 16 + lq;
            float v0 = acc[mt][nt][0] + b0v;
            float v1 = acc[mt][nt][1] + b1v;
            float v2 = acc[mt][nt][2] + b0v;
            float v3 = acc[mt][nt][3] + b1v;
            if (ACT == 1) { v0 = tanhf(v0); v1 = tanhf(v1); v2 = tanhf(v2); v3 = tanhf(v3); }
            *(float2*)(C + (size_t)r0 * N + c)       = make_float2(v0, v1);
            *(float2*)(C + (size_t)(r0 + 8) * N + c) = make_float2(v2, v3);
        }
    }
}

// ---------------- weight transpose with tf32 rounding ----------------
__global__ void transpose_k(const float* __restrict__ src, float* __restrict__ dst, int R, int Cc)
{
    __shared__ float t[32][33];
    int r0 = blockIdx.y * 32, c0 = blockIdx.x * 32;
    t[threadIdx.y][threadIdx.x] = src[(size_t)(r0 + threadIdx.y) * Cc + c0 + threadIdx.x];
    __syncthreads();
    dst[(size_t)(c0 + threadIdx.y) * R + r0 + threadIdx.x] =
        __uint_as_float(f2tf32(t[threadIdx.x][threadIdx.y]));
}

// ---------------- persistent LSTM (3xTF32 split, ldmatrix, split acc chains) ----------------
#define WSTR 516
#define HSTR 68
#define SMEM_LSTM ((2 * 32 * WSTR) * 4 + (2 * 128 * HSTR) * 4)

__global__ __launch_bounds__(256, 1)
void lstm_mma(const float* __restrict__ xpF, const float* __restrict__ xpB,
              const float* __restrict__ whF, const float* __restrict__ whB,
              float* __restrict__ hout, float* __restrict__ houtr, int round_out)
{
    extern __shared__ uint32_t smem[];
    uint32_t* sWhi = smem;                      // 32 x WSTR (tf32)
    uint32_t* sWlo = smem + 32 * WSTR;
    float* sH = (float*)(smem + 2 * 32 * WSTR); // [2][128*HSTR] raw fp32
    __shared__ unsigned s_gen;

    const int tid  = threadIdx.x;
    const int bi   = blockIdx.x;
    const int w    = tid >> 5;
    const int lane = tid & 31;
    const int lq   = lane >> 2;
    const int lr   = lane & 3;
    const int g    = lane >> 3;
    const int r8   = lane & 7;
    const int dir  = bi >> 6;
    const int j0   = (bi & 63) * 8;
    const int w16  = w * 16;
    const float* wh = dir ? whB : whF;
    const float* xp = dir ? xpB : xpF;
    const uint32_t sH_base   = smem_u32(sH);
    const uint32_t sWhi_base = smem_u32(sWhi);
    const uint32_t sWlo_base = smem_u32(sWlo);

    // ldmatrix per-thread row offsets (bytes)
    const uint32_t hRowOff = (uint32_t)((w16 + r8 + ((g & 1) << 3)) * HSTR) * 4 + ((g >> 1) << 4);
    const uint32_t wRowOff = (uint32_t)((((g >> 1) << 3) + r8) * WSTR) * 4 + ((g & 1) << 4);

    // load W tile (gate-row layout), split hi/lo once
    for (int e = tid; e < 32 * 512; e += 256) {
        int n = e >> 9, k = e & 511;
        int grow = (n >> 3) * 512 + j0 + (n & 7);
        float v = wh[(size_t)grow * HH + k];
        uint32_t hi = f2tf32(v);
        uint32_t lo = f2tf32(v - __uint_as_float(hi));
        sWhi[n * WSTR + k] = hi;
        sWlo[n * WSTR + k] = lo;
    }
    __syncthreads();

    float creg[4] = {0.f, 0.f, 0.f, 0.f};

    // prefetch xproj for t=0
    float2 xg2[2][4];
#pragma unroll
    for (int bb = 0; bb < 2; bb++) {
        const float* xr = xp + ((size_t)(w16 + lq + bb * 8) * TT + 0) * GG + j0 + lr * 2;
        xg2[bb][0] = *(const float2*)(xr);
        xg2[bb][1] = *(const float2*)(xr + 512);
        xg2[bb][2] = *(const float2*)(xr + 1024);
        xg2[bb][3] = *(const float2*)(xr + 1536);
    }

    for (int t = 0; t < TT; t++) {
        float acc2[2][16];
#pragma unroll
        for (int pb = 0; pb < 2; pb++)
#pragma unroll
            for (int r = 0; r < 16; r++) acc2[pb][r] = 0.f;

        if (t > 0) {
            const float* hprev = g_hping + ((((t - 1) & 1) << 1) + dir) * (BB * HH);

            auto load_hchunk = [&](int kc, int buf) {
                const uint32_t boff = (uint32_t)buf * 128 * HSTR * 4;
#pragma unroll
                for (int i = 0; i < 8; i++) {
                    int s   = tid + i * 256;
                    int row = s >> 4;
                    int c4  = s & 15;
                    cp_async16(sH_base + boff + (uint32_t)(row * HSTR + c4 * 4) * 4,
                               hprev + row * 512 + kc * 64 + c4 * 4, 16);
                }
                cp_commit();
            };

            load_hchunk(0, 0);
            for (int kc = 0; kc < 8; kc++) {
                cp_wait0();
                __syncthreads();
                if (kc < 7) load_hchunk(kc + 1, (kc + 1) & 1);

                const uint32_t bH = sH_base + (uint32_t)(kc & 1) * 128 * HSTR * 4;
                float* accp = acc2[kc & 1];
#pragma unroll
                for (int ks = 0; ks < 8; ks++) {
                    uint32_t v0u, v1u, v2u, v3u;
                    LDSM4(v0u, v1u, v2u, v3u, bH + hRowOff + ks * 32);
                    float v0 = __uint_as_float(v0u), v1 = __uint_as_float(v1u);
                    float v2 = __uint_as_float(v2u), v3 = __uint_as_float(v3u);
                    uint32_t ahi[4], alo[4];
                    ahi[0] = f2tf32(v0); alo[0] = f2tf32(v0 - __uint_as_float(ahi[0]));
                    ahi[1] = f2tf32(v1); alo[1] = f2tf32(v1 - __uint_as_float(ahi[1]));
                    ahi[2] = f2tf32(v2); alo[2] = f2tf32(v2 - __uint_as_float(ahi[2]));
                    ahi[3] = f2tf32(v3); alo[3] = f2tf32(v3 - __uint_as_float(ahi[3]));
                    const uint32_t kgb = (uint32_t)kc * 256 + (uint32_t)ks * 32;
#pragma unroll
                    for (int p = 0; p < 2; p++) {
                        uint32_t bh[4], bl[4];
                        LDSM4(bh[0], bh[1], bh[2], bh[3],
                              sWhi_base + wRowOff + (uint32_t)(p * 16 * WSTR) * 4 + kgb);
                        LDSM4(bl[0], bl[1], bl[2], bl[3],
                              sWlo_base + wRowOff + (uint32_t)(p * 16 * WSTR) * 4 + kgb);
                        uint32_t bhi0[2] = {bh[0], bh[1]}, bhi1[2] = {bh[2], bh[3]};
                        uint32_t blo0[2] = {bl[0], bl[1]}, blo1[2] = {bl[2], bl[3]};
                        float* a0 = accp + (2 * p) * 4;
                        float* a1 = accp + (2 * p + 1) * 4;
                        mma_tf32(a0, ahi, bhi0);
                        mma_tf32(a0, alo, bhi0);
                        mma_tf32(a0, ahi, blo0);
                        mma_tf32(a1, ahi, bhi1);
                        mma_tf32(a1, alo, bhi1);
                        mma_tf32(a1, ahi, blo1);
                    }
                }
                __syncthreads();
            }
        }

        // combine split accumulators
        float accv[4][4];
#pragma unroll
        for (int nt = 0; nt < 4; nt++)
#pragma unroll
            for (int r = 0; r < 4; r++)
                accv[nt][r] = acc2[0][nt * 4 + r] + acc2[1][nt * 4 + r];

        // epilogue: gates + c in registers
        const int tt = dir ? (TT - 1 - t) : t;
        float* hnext = g_hping + (((t & 1) << 1) + dir) * (BB * HH);
#pragma unroll
        for (int bb = 0; bb < 2; bb++) {
            int b = w16 + lq + bb * 8;
            int i0 = bb * 2;

            float zi = accv[0][i0] + xg2[bb][0].x, zf = accv[1][i0] + xg2[bb][1].x;
            float zg = accv[2][i0] + xg2[bb][2].x, zo = accv[3][i0] + xg2[bb][3].x;
            float si = 1.f / (1.f + __expf(-zi));
            float sf = 1.f / (1.f + __expf(-zf));
            float so = 1.f / (1.f + __expf(-zo));
            float tg = tanhf(zg);
            creg[i0] = sf * creg[i0] + si * tg;
            float h0v = so * tanhf(creg[i0]);

            zi = accv[0][i0 + 1] + xg2[bb][0].y; zf = accv[1][i0 + 1] + xg2[bb][1].y;
            zg = accv[2][i0 + 1] + xg2[bb][2].y; zo = accv[3][i0 + 1] + xg2[bb][3].y;
            si = 1.f / (1.f + __expf(-zi));
            sf = 1.f / (1.f + __expf(-zf));
            so = 1.f / (1.f + __expf(-zo));
            tg = tanhf(zg);
            creg[i0 + 1] = sf * creg[i0 + 1] + si * tg;
            float h1v = so * tanhf(creg[i0 + 1]);

            float2 hv = make_float2(h0v, h1v);
            *(float2*)(hnext + b * 512 + j0 + lr * 2) = hv;
            float2 ho = round_out
                ? make_float2(__uint_as_float(f2tf32(h0v)), __uint_as_float(f2tf32(h1v)))
                : hv;
            *(float2*)(hout + ((size_t)b * TT + tt) * HD2 + dir * 512 + j0 + lr * 2) = ho;
            if (houtr) {
                float2 hr = make_float2(__uint_as_float(f2tf32(h0v)), __uint_as_float(f2tf32(h1v)));
                *(float2*)(houtr + ((size_t)b * TT + tt) * HD2 + dir * 512 + j0 + lr * 2) = hr;
            }
        }

        // barrier: arrive
        __syncthreads();
        if (tid == 0) {
            __threadfence();
            s_gen = atomicAdd(&g_bgen2[dir], 0u);
            if (atomicAdd(&g_bcnt2[dir], 1u) == 63u) {
                atomicExch(&g_bcnt2[dir], 0u);
                __threadfence();
                atomicAdd(&g_bgen2[dir], 1u);
            }
        }

        // prefetch xproj for t+1 (independent of barrier)
        if (t + 1 < TT) {
#pragma unroll
            for (int bb = 0; bb < 2; bb++) {
                const float* xr = xp + ((size_t)(w16 + lq + bb * 8) * TT + (t + 1)) * GG + j0 + lr * 2;
                xg2[bb][0] = *(const float2*)(xr);
                xg2[bb][1] = *(const float2*)(xr + 512);
                xg2[bb][2] = *(const float2*)(xr + 1024);
                xg2[bb][3] = *(const float2*)(xr + 1536);
            }
        }

        // barrier: wait
        if (tid == 0) {
            unsigned gv = s_gen;
            while (atomicAdd(&g_bgen2[dir], 0u) == gv) { __nanosleep(20); }
        }
        __syncthreads();
    }
}

// ---------------- tail kernels ----------------
__global__ void scores_k(const float* __restrict__ th, const float* __restrict__ aw2,
                         const float* __restrict__ ab2, float* __restrict__ sc)
{
    int r = blockIdx.x;
    const float* row = th + (size_t)r * HD2;
    float s = 0.f;
    for (int k = threadIdx.x; k < HD2; k += 128) s += row[k] * aw2[k];
    __shared__ float red[128];
    red[threadIdx.x] = s; __syncthreads();
    for (int o = 64; o > 0; o >>= 1) {
        if (threadIdx.x < o) red[threadIdx.x] += red[threadIdx.x + o];
        __syncthreads();
    }
    if (threadIdx.x == 0) sc[r] = red[0] + ab2[0];
}

__global__ void softmax_k(const float* __restrict__ sc, float* __restrict__ attw,
                          float* __restrict__ out_attw)
{
    int b = blockIdx.x, t = threadIdx.x;
    float v = sc[b * TT + t];
    __shared__ float red[TT];
    red[t] = v; __syncthreads();
    for (int o = 128; o > 0; o >>= 1) {
        if (t < o) red[t] = fmaxf(red[t], red[t + o]);
        __syncthreads();
    }
    float mx = red[0]; __syncthreads();
    float e = __expf(v - mx);
    red[t] = e; __syncthreads();
    for (int o = 128; o > 0; o >>= 1) {
        if (t < o) red[t] += red[t + o];
        __syncthreads();
    }
    float w = e / red[0];
    attw[b * TT + t] = w;
    if (out_attw) out_attw[b * TT + t] = w;
}

__global__ void context_k(const float* __restrict__ attw, const float* __restrict__ lo,
                          float* __restrict__ ctx)
{
    int b = blockIdx.y;
    int n = blockIdx.x * 256 + threadIdx.x;
    __shared__ float aw[TT];
    aw[threadIdx.x] = attw[b * TT + threadIdx.x];
    __syncthreads();
    float s = 0.f;
    const float* base = lo + (size_t)b * TT * HD2 + n;
#pragma unroll 4
    for (int t = 0; t < TT; t++) s += aw[t] * base[(size_t)t * HD2];
    ctx[b * HD2 + n] = s;
}

__global__ void cls1_k(const float* __restrict__ ctx, const float* __restrict__ w,
                       const float* __restrict__ bias, float* __restrict__ hc)
{
    int b = blockIdx.x, j = threadIdx.x;
    __shared__ float xs[HD2];
    xs[j] = ctx[b * HD2 + j];
    xs[j + 512] = ctx[b * HD2 + j + 512];
    __syncthreads();
    float s = bias[j];
    for (int k = 0; k < HD2; k++) s += xs[k] * w[k * HH + j];
    hc[b * HH + j] = fmaxf(s, 0.f);
}

__global__ void cls2_k(const float* __restrict__ hc, const float* __restrict__ w,
                       const float* __restrict__ bias, float* __restrict__ out)
{
    int b = blockIdx.x, j = threadIdx.x;
    __shared__ float xs[HH];
    for (int k = j; k < HH; k += 128) xs[k] = hc[b * HH + k];
    __syncthreads();
    if (j < NC) {
        float s = bias[j];
        for (int k = 0; k < HH; k++) s += xs[k] * w[k * NC + j];
        out[b * NC + j] = s;
    }
}

// ---------------- launch ----------------
extern "C" void kernel_launch(void* const* d_in, const int* in_sizes, int n_in,
                              void* d_out, int out_size)
{
    const float* x     = (const float*)d_in[0];
    const float* wih0f = (const float*)d_in[1];
    const float* whh0f = (const float*)d_in[2];
    const float* b0f   = (const float*)d_in[3];
    const float* wih0b = (const float*)d_in[4];
    const float* whh0b = (const float*)d_in[5];
    const float* b0b   = (const float*)d_in[6];
    const float* wih1f = (const float*)d_in[7];
    const float* whh1f = (const float*)d_in[8];
    const float* b1f   = (const float*)d_in[9];
    const float* wih1b = (const float*)d_in[10];
    const float* whh1b = (const float*)d_in[11];
    const float* b1b   = (const float*)d_in[12];
    const float* aw1   = (const float*)d_in[13];
    const float* ab1   = (const float*)d_in[14];
    const float* aw2   = (const float*)d_in[15];
    const float* ab2   = (const float*)d_in[16];
    const float* cw1   = (const float*)d_in[17];
    const float* cb1   = (const float*)d_in[18];
    const float* cw2   = (const float*)d_in[19];
    const float* cb2   = (const float*)d_in[20];
    float* out = (float*)d_out;

    float *xpf, *xpb, *h0, *lo, *lor, *awt, *xr, *w0f, *w0b, *w1f, *w1b, *sc, *aw, *ctx, *hc;
    cudaGetSymbolAddress((void**)&xpf, g_xpf);
    cudaGetSymbolAddress((void**)&xpb, g_xpb);
    cudaGetSymbolAddress((void**)&h0,  g_h0buf);
    cudaGetSymbolAddress((void**)&lo,  g_outbuf);
    cudaGetSymbolAddress((void**)&lor, g_lor);
    cudaGetSymbolAddress((void**)&awt, g_awt);
    cudaGetSymbolAddress((void**)&xr,  g_xr);
    cudaGetSymbolAddress((void**)&w0f, g_w0f);
    cudaGetSymbolAddress((void**)&w0b, g_w0b);
    cudaGetSymbolAddress((void**)&w1f, g_w1f);
    cudaGetSymbolAddress((void**)&w1b, g_w1b);
    cudaGetSymbolAddress((void**)&sc,  g_scoresb);
    cudaGetSymbolAddress((void**)&aw,  g_attwb);
    cudaGetSymbolAddress((void**)&ctx, g_ctx);
    cudaGetSymbolAddress((void**)&hc,  g_hc);

    cudaFuncSetAttribute(gemm_mma<0, 0>, cudaFuncAttributeMaxDynamicSharedMemorySize, GSMEM);
    cudaFuncSetAttribute(gemm_mma<1, 0>, cudaFuncAttributeMaxDynamicSharedMemorySize, GSMEM);
    cudaFuncSetAttribute(gemm_mma<0, 1>, cudaFuncAttributeMaxDynamicSharedMemorySize, GSMEM);
    cudaFuncSetAttribute(lstm_mma, cudaFuncAttributeMaxDynamicSharedMemorySize, SMEM_LSTM);

    // rounding passes
    round_k<<<1024, 256>>>((const float4*)x,     (float4*)xr,  BT * INN / 4);
    round_k<<<512, 256>>>((const float4*)wih0f, (float4*)w0f, GG * INN / 4);
    round_k<<<512, 256>>>((const float4*)wih0b, (float4*)w0b, GG * INN / 4);
    round_k<<<512, 256>>>((const float4*)wih1f, (float4*)w1f, GG * HD2 / 4);
    round_k<<<512, 256>>>((const float4*)wih1b, (float4*)w1b, GG * HD2 / 4);
    transpose_k<<<dim3(HD2 / 32, HD2 / 32), dim3(32, 32)>>>(aw1, awt, HD2, HD2);

    dim3 blk(256);
    dim3 gp(GG / 128, BT / 128);      // 16 x 256

    gemm_mma<0, 0><<<gp, blk, GSMEM>>>(xr, w0f, b0f, xpf, BT, GG, INN);
    gemm_mma<1, 0><<<gp, blk, GSMEM>>>(xr, w0b, b0b, xpb, BT, GG, INN);
    lstm_mma<<<128, 256, SMEM_LSTM>>>(xpf, xpb, whh0f, whh0b, h0, nullptr, 1);

    gemm_mma<0, 0><<<gp, blk, GSMEM>>>(h0, w1f, b1f, xpf, BT, GG, HD2);
    gemm_mma<1, 0><<<gp, blk, GSMEM>>>(h0, w1b, b1b, xpb, BT, GG, HD2);
    lstm_mma<<<128, 256, SMEM_LSTM>>>(xpf, xpb, whh1f, whh1b, lo, lor, 0);

    dim3 ga(HD2 / 128, BT / 128);     // 8 x 256
    gemm_mma<0, 1><<<ga, blk, GSMEM>>>(lor, awt, ab1, xpf, BT, HD2, HD2);
    scores_k<<<BT, 128>>>(xpf, aw2, ab2, sc);

    float* out_attw = (out_size >= (BB * NC + BT)) ? (out + BB * NC) : nullptr;
    softmax_k<<<BB, TT>>>(sc, aw, out_attw);
    context_k<<<dim3(HD2 / 256, BB), 256>>>(aw, lo, ctx);
    cls1_k<<<BB, 512>>>(ctx, cw1, cb1, hc);
    cls2_k<<<BB, 128>>>(hc, cw2, cb2, out);
}

// round 10
// speedup vs baseline: 1.2298x; 1.2298x over previous
#include <cuda_runtime.h>
#include <cuda_bf16.h>
#include <cstdint>

// Problem dims
#define BB   128
#define TT   256
#define HH   512
#define GG   2048
#define INN  1662
#define HD2  1024
#define NC   100
#define BT   32768

// ---------------- device scratch ----------------
__device__ float g_xpf[BT * GG];
__device__ float g_xpb[BT * GG];
__device__ float g_h0buf[BT * HD2];       // layer0 h (tf32-rounded)
__device__ float g_outbuf[BT * HD2];      // lstm_out fp32
__device__ float g_lor[BT * HD2];         // lstm_out tf32-rounded
__device__ float g_awt[HD2 * HD2];
__device__ float g_xr[BT * INN];
__device__ float g_w0f[GG * INN];
__device__ float g_w0b[GG * INN];
__device__ float g_w1f[GG * HD2];
__device__ float g_w1b[GG * HD2];
__device__ float g_hping[4 * BB * HH];
__device__ float g_scoresb[BT];
__device__ float g_attwb[BT];
__device__ float g_ctx[BB * HD2];
__device__ float g_hc[BB * HH];

__device__ unsigned g_bcnt2[2] = {0, 0};
__device__ unsigned g_bgen2[2] = {0, 0};

__device__ __forceinline__ uint32_t f2tf32(float x) {
    uint32_t u;
    asm("cvt.rna.tf32.f32 %0, %1;" : "=r"(u) : "f"(x));
    return u;
}

__device__ __forceinline__ void mma_tf32(float* d, const uint32_t* a, const uint32_t* b) {
    asm volatile(
        "mma.sync.aligned.m16n8k8.row.col.f32.tf32.tf32.f32 "
        "{%0,%1,%2,%3}, {%4,%5,%6,%7}, {%8,%9}, {%0,%1,%2,%3};"
        : "+f"(d[0]), "+f"(d[1]), "+f"(d[2]), "+f"(d[3])
        : "r"(a[0]), "r"(a[1]), "r"(a[2]), "r"(a[3]), "r"(b[0]), "r"(b[1]));
}

__device__ __forceinline__ void mma_bf16(float* d, const uint32_t* a, const uint32_t* b) {
    asm volatile(
        "mma.sync.aligned.m16n8k16.row.col.f32.bf16.bf16.f32 "
        "{%0,%1,%2,%3}, {%4,%5,%6,%7}, {%8,%9}, {%0,%1,%2,%3};"
        : "+f"(d[0]), "+f"(d[1]), "+f"(d[2]), "+f"(d[3])
        : "r"(a[0]), "r"(a[1]), "r"(a[2]), "r"(a[3]), "r"(b[0]), "r"(b[1]));
}

__device__ __forceinline__ uint32_t smem_u32(const void* p) {
    uint32_t a;
    asm("{ .reg .u64 t; cvta.to.shared.u64 t, %1; cvt.u32.u64 %0, t; }" : "=r"(a) : "l"(p));
    return a;
}
__device__ __forceinline__ void cp_async16(uint32_t dst, const void* src, int src_bytes) {
    asm volatile("cp.async.cg.shared.global [%0], [%1], 16, %2;"
                 :: "r"(dst), "l"(src), "r"(src_bytes) : "memory");
}
__device__ __forceinline__ void cp_async8(uint32_t dst, const void* src, int src_bytes) {
    asm volatile("cp.async.ca.shared.global [%0], [%1], 8, %2;"
                 :: "r"(dst), "l"(src), "r"(src_bytes) : "memory");
}
__device__ __forceinline__ void cp_commit() {
    asm volatile("cp.async.commit_group;" ::: "memory");
}
__device__ __forceinline__ void cp_wait0() {
    asm volatile("cp.async.wait_group 0;" ::: "memory");
}

// split a float2 (k0,k1) into packed bf16x2 hi and residual-lo registers
// (low 16 bits hold the lower-k element, matching mma fragment order)
__device__ __forceinline__ void split_bf16x2(float2 p, uint32_t& hi, uint32_t& lo) {
    __nv_bfloat162 h2 = __floats2bfloat162_rn(p.x, p.y);
    uint32_t hu; memcpy(&hu, &h2, 4);
    float f0 = __uint_as_float(hu << 16);
    float f1 = __uint_as_float(hu & 0xFFFF0000u);
    __nv_bfloat162 l2 = __floats2bfloat162_rn(p.x - f0, p.y - f1);
    uint32_t lu; memcpy(&lu, &l2, 4);
    hi = hu; lo = lu;
}

// ---------------- rounding pass ----------------
__global__ void round_k(const float4* __restrict__ src, float4* __restrict__ dst, int n4)
{
    int stride = gridDim.x * blockDim.x;
    for (int i = blockIdx.x * blockDim.x + threadIdx.x; i < n4; i += stride) {
        float4 v = src[i];
        v.x = __uint_as_float(f2tf32(v.x));
        v.y = __uint_as_float(f2tf32(v.y));
        v.z = __uint_as_float(f2tf32(v.z));
        v.w = __uint_as_float(f2tf32(v.w));
        dst[i] = v;
    }
}

// ---------------- tf32 GEMM (R8-exact): chunk32, cp.async double-buffered ----------------
#define SSTR 36
#define GSMEM (2 * 2 * 128 * SSTR * 4)

template<int FLIP, int ACT>
__global__ __launch_bounds__(256, 2)
void gemm_mma(const float* __restrict__ A, const float* __restrict__ W,
              const float* __restrict__ bias, float* __restrict__ C,
              int M, int N, int K)
{
    extern __shared__ float dsm[];
    float* sA = dsm;
    float* sB = dsm + 2 * 128 * SSTR;

    const int tid  = threadIdx.x;
    const int wid  = tid >> 5;
    const int lane = tid & 31;
    const int wm   = wid & 1;
    const int wn   = wid >> 1;
    const int m0 = blockIdx.y * 128;
    const int n0 = blockIdx.x * 128;
    const int lq = lane >> 2;
    const int lr = lane & 3;

    const uint32_t sA_base = smem_u32(sA);
    const uint32_t sB_base = smem_u32(sB);
    const bool use16 = ((K & 3) == 0);

    float acc[4][4][4];
#pragma unroll
    for (int i = 0; i < 4; i++)
#pragma unroll
        for (int j = 0; j < 4; j++)
#pragma unroll
            for (int r = 0; r < 4; r++) acc[i][j][r] = 0.f;

    const int nk = (K + 31) / 32;

    auto arow_of = [&](int r) {
        int gm = m0 + r;
        if (FLIP) { int bI = gm >> 8; int t = gm & 255; return (bI << 8) + (255 - t); }
        return gm;
    };

    auto load_chunk16 = [&](int kc, int buf) {
        const int k0 = kc * 32;
        const uint32_t boff = (uint32_t)buf * 128 * SSTR * 4;
#pragma unroll
        for (int i = 0; i < 4; i++) {
            int s  = tid + i * 256;
            int r  = s >> 3;
            int c4 = s & 7;
            int k  = k0 + c4 * 4;
            int nbf = K - k; nbf = nbf < 0 ? 0 : (nbf > 4 ? 4 : nbf);
            int bytes = nbf * 4;
            int ksrc = (k < K) ? k : 0;
            uint32_t soff = (uint32_t)(r * SSTR + c4 * 4) * 4;
            cp_async16(sA_base + boff + soff, A + (size_t)arow_of(r) * K + ksrc, bytes);
            cp_async16(sB_base + boff + soff, W + (size_t)(n0 + r) * K + ksrc, bytes);
        }
        cp_commit();
    };

    auto load_chunk8 = [&](int kc, int buf) {
        const int k0 = kc * 32;
        const uint32_t boff = (uint32_t)buf * 128 * SSTR * 4;
#pragma unroll
        for (int i = 0; i < 8; i++) {
            int s  = tid + i * 256;
            int r  = s >> 4;
            int c2 = s & 15;
            int k  = k0 + c2 * 2;
            int nbf = K - k; nbf = nbf < 0 ? 0 : (nbf > 2 ? 2 : nbf);
            int bytes = nbf * 4;
            int ksrc = (k < K) ? k : 0;
            uint32_t soff = (uint32_t)(r * SSTR + c2 * 2) * 4;
            cp_async8(sA_base + boff + soff, A + (size_t)arow_of(r) * K + ksrc, bytes);
            cp_async8(sB_base + boff + soff, W + (size_t)(n0 + r) * K + ksrc, bytes);
        }
        cp_commit();
    };

    auto load_chunk = [&](int kc, int buf) {
        if (use16) load_chunk16(kc, buf); else load_chunk8(kc, buf);
    };

    load_chunk(0, 0);

    for (int kc = 0; kc < nk; kc++) {
        cp_wait0();
        __syncthreads();
        if (kc + 1 < nk) load_chunk(kc + 1, (kc + 1) & 1);

        const float* bA = sA + (kc & 1) * 128 * SSTR;
        const float* bB = sB + (kc & 1) * 128 * SSTR;
#pragma unroll
        for (int ks = 0; ks < 4; ks++) {
            const int kb = ks * 8 + lr;
            uint32_t af[4][4];
#pragma unroll
            for (int mt = 0; mt < 4; mt++) {
                int base = wm * 64 + mt * 16 + lq;
                af[mt][0] = __float_as_uint(bA[ base      * SSTR + kb]);
                af[mt][1] = __float_as_uint(bA[(base + 8) * SSTR + kb]);
                af[mt][2] = __float_as_uint(bA[ base      * SSTR + kb + 4]);
                af[mt][3] = __float_as_uint(bA[(base + 8) * SSTR + kb + 4]);
            }
            uint32_t bf[4][2];
#pragma unroll
            for (int nt = 0; nt < 4; nt++) {
                int brow = wn * 32 + nt * 8 + lq;
                bf[nt][0] = __float_as_uint(bB[brow * SSTR + kb]);
                bf[nt][1] = __float_as_uint(bB[brow * SSTR + kb + 4]);
            }
#pragma unroll
            for (int mt = 0; mt < 4; mt++)
#pragma unroll
                for (int nt = 0; nt < 4; nt++)
                    mma_tf32(acc[mt][nt], af[mt], bf[nt]);
        }
        __syncthreads();
    }

    const int rbase = m0 + wm * 64;
    const int cbase = n0 + wn * 32;
#pragma unroll
    for (int mt = 0; mt < 4; mt++) {
#pragma unroll
        for (int nt = 0; nt < 4; nt++) {
            int c  = cbase + nt * 8 + lr * 2;
            float b0v = bias[c], b1v = bias[c + 1];
            int r0 = rbase + mt * 16 + lq;
            float v0 = acc[mt][nt][0] + b0v;
            float v1 = acc[mt][nt][1] + b1v;
            float v2 = acc[mt][nt][2] + b0v;
            float v3 = acc[mt][nt][3] + b1v;
            if (ACT == 1) { v0 = tanhf(v0); v1 = tanhf(v1); v2 = tanhf(v2); v3 = tanhf(v3); }
            *(float2*)(C + (size_t)r0 * N + c)       = make_float2(v0, v1);
            *(float2*)(C + (size_t)(r0 + 8) * N + c) = make_float2(v2, v3);
        }
    }
}

// ---------------- weight transpose with tf32 rounding ----------------
__global__ void transpose_k(const float* __restrict__ src, float* __restrict__ dst, int R, int Cc)
{
    __shared__ float t[32][33];
    int r0 = blockIdx.y * 32, c0 = blockIdx.x * 32;
    t[threadIdx.y][threadIdx.x] = src[(size_t)(r0 + threadIdx.y) * Cc + c0 + threadIdx.x];
    __syncthreads();
    dst[(size_t)(c0 + threadIdx.y) * R + r0 + threadIdx.x] =
        __uint_as_float(f2tf32(t[threadIdx.x][threadIdx.y]));
}

// ---------------- persistent LSTM: bf16 hi/lo split (m16n8k16), cp.async h ----------------
// W resident in smem as bf16 hi/lo planes in chunked layout [8][32][104].
// h staged raw fp32 (stride 72), split to bf16 hi/lo at fragment-load time.
// Per K=16: 3 bf16 MMAs replace 6 tf32 split MMAs.  Structure otherwise = R8.
#define WPLANE (8 * 32 * 104)                 // bf16 elems per plane
#define HSTRL 72                              // fp32 stride for h chunk rows
#define SMEM_LSTM (2 * WPLANE * 2 + 2 * 128 * HSTRL * 4)   // 106496 + 73728

__global__ __launch_bounds__(256, 1)
void lstm_mma(const float* __restrict__ xpF, const float* __restrict__ xpB,
              const float* __restrict__ whF, const float* __restrict__ whB,
              float* __restrict__ hout, float* __restrict__ houtr, int round_out)
{
    extern __shared__ char smemc[];
    __nv_bfloat16* sWhi = (__nv_bfloat16*)smemc;
    __nv_bfloat16* sWlo = sWhi + WPLANE;
    float* sH = (float*)(smemc + 2 * WPLANE * 2);
    __shared__ unsigned s_gen;

    const int tid  = threadIdx.x;
    const int bi   = blockIdx.x;
    const int w    = tid >> 5;
    const int lane = tid & 31;
    const int lq   = lane >> 2;
    const int lr   = lane & 3;
    const int dir  = bi >> 6;
    const int j0   = (bi & 63) * 8;
    const int w16  = w * 16;
    const float* wh = dir ? whB : whF;
    const float* xp = dir ? xpB : xpF;
    const uint32_t sH_base = smem_u32(sH);

    // load W tile (gate-row layout) into chunked bf16 hi/lo planes
    for (int e = tid; e < 32 * 512; e += 256) {
        int n = e >> 9, k = e & 511;
        int c = k >> 6, kin = k & 63;
        int grow = (n >> 3) * 512 + j0 + (n & 7);
        float v = wh[(size_t)grow * HH + k];
        __nv_bfloat16 hb = __float2bfloat16_rn(v);
        float hf = __bfloat162float(hb);
        __nv_bfloat16 lb = __float2bfloat16_rn(v - hf);
        int idx = (c * 32 + n) * 104 + kin;
        sWhi[idx] = hb;
        sWlo[idx] = lb;
    }
    __syncthreads();

    float creg[4] = {0.f, 0.f, 0.f, 0.f};

    // prefetch xproj for t=0
    float2 xg2[2][4];
#pragma unroll
    for (int bb = 0; bb < 2; bb++) {
        const float* xr = xp + ((size_t)(w16 + lq + bb * 8) * TT + 0) * GG + j0 + lr * 2;
        xg2[bb][0] = *(const float2*)(xr);
        xg2[bb][1] = *(const float2*)(xr + 512);
        xg2[bb][2] = *(const float2*)(xr + 1024);
        xg2[bb][3] = *(const float2*)(xr + 1536);
    }

    for (int t = 0; t < TT; t++) {
        float acc[4][4];
#pragma unroll
        for (int nt = 0; nt < 4; nt++)
#pragma unroll
            for (int r = 0; r < 4; r++) acc[nt][r] = 0.f;

        if (t > 0) {
            const float* hprev = g_hping + ((((t - 1) & 1) << 1) + dir) * (BB * HH);

            auto load_hchunk = [&](int kc, int buf) {
                const uint32_t boff = (uint32_t)buf * 128 * HSTRL * 4;
#pragma unroll
                for (int i = 0; i < 8; i++) {
                    int s   = tid + i * 256;
                    int row = s >> 4;
                    int c4  = s & 15;
                    cp_async16(sH_base + boff + (uint32_t)(row * HSTRL + c4 * 4) * 4,
                               hprev + row * 512 + kc * 64 + c4 * 4, 16);
                }
                cp_commit();
            };

            load_hchunk(0, 0);
            for (int kc = 0; kc < 8; kc++) {
                cp_wait0();
                __syncthreads();
                if (kc < 7) load_hchunk(kc + 1, (kc + 1) & 1);

                const float* bH = sH + (kc & 1) * 128 * HSTRL;
                const __nv_bfloat16* Wchi = sWhi + kc * 32 * 104;
                const __nv_bfloat16* Wclo = sWlo + kc * 32 * 104;
#pragma unroll
                for (int ks = 0; ks < 4; ks++) {
                    const int kk = ks * 16 + 2 * lr;
                    const float* hr0 = bH + (w16 + lq)     * HSTRL;
                    const float* hr1 = bH + (w16 + lq + 8) * HSTRL;
                    float2 p00 = *(const float2*)(hr0 + kk);
                    float2 p10 = *(const float2*)(hr1 + kk);
                    float2 p01 = *(const float2*)(hr0 + kk + 8);
                    float2 p11 = *(const float2*)(hr1 + kk + 8);
                    uint32_t ahi[4], alo[4];
                    split_bf16x2(p00, ahi[0], alo[0]);
                    split_bf16x2(p10, ahi[1], alo[1]);
                    split_bf16x2(p01, ahi[2], alo[2]);
                    split_bf16x2(p11, ahi[3], alo[3]);
#pragma unroll
                    for (int nt = 0; nt < 4; nt++) {
                        const __nv_bfloat16* wr_hi = Wchi + (nt * 8 + lq) * 104 + kk;
                        const __nv_bfloat16* wr_lo = Wclo + (nt * 8 + lq) * 104 + kk;
                        uint32_t bhi[2], blo[2];
                        bhi[0] = *(const uint32_t*)(wr_hi);
                        bhi[1] = *(const uint32_t*)(wr_hi + 8);
                        blo[0] = *(const uint32_t*)(wr_lo);
                        blo[1] = *(const uint32_t*)(wr_lo + 8);
                        mma_bf16(acc[nt], ahi, bhi);
                        mma_bf16(acc[nt], alo, bhi);
                        mma_bf16(acc[nt], ahi, blo);
                    }
                }
                __syncthreads();
            }
        }

        // epilogue: gates + c in registers
        const int tt = dir ? (TT - 1 - t) : t;
        float* hnext = g_hping + (((t & 1) << 1) + dir) * (BB * HH);
#pragma unroll
        for (int bb = 0; bb < 2; bb++) {
            int b = w16 + lq + bb * 8;
            int i0 = bb * 2;

            float zi = acc[0][i0] + xg2[bb][0].x, zf = acc[1][i0] + xg2[bb][1].x;
            float zg = acc[2][i0] + xg2[bb][2].x, zo = acc[3][i0] + xg2[bb][3].x;
            float si = 1.f / (1.f + __expf(-zi));
            float sf = 1.f / (1.f + __expf(-zf));
            float so = 1.f / (1.f + __expf(-zo));
            float tg = tanhf(zg);
            creg[i0] = sf * creg[i0] + si * tg;
            float h0v = so * tanhf(creg[i0]);

            zi = acc[0][i0 + 1] + xg2[bb][0].y; zf = acc[1][i0 + 1] + xg2[bb][1].y;
            zg = acc[2][i0 + 1] + xg2[bb][2].y; zo = acc[3][i0 + 1] + xg2[bb][3].y;
            si = 1.f / (1.f + __expf(-zi));
            sf = 1.f / (1.f + __expf(-zf));
            so = 1.f / (1.f + __expf(-zo));
            tg = tanhf(zg);
            creg[i0 + 1] = sf * creg[i0 + 1] + si * tg;
            float h1v = so * tanhf(creg[i0 + 1]);

            float2 hv = make_float2(h0v, h1v);
            *(float2*)(hnext + b * 512 + j0 + lr * 2) = hv;
            float2 ho = round_out
                ? make_float2(__uint_as_float(f2tf32(h0v)), __uint_as_float(f2tf32(h1v)))
                : hv;
            *(float2*)(hout + ((size_t)b * TT + tt) * HD2 + dir * 512 + j0 + lr * 2) = ho;
            if (houtr) {
                float2 hr = make_float2(__uint_as_float(f2tf32(h0v)), __uint_as_float(f2tf32(h1v)));
                *(float2*)(houtr + ((size_t)b * TT + tt) * HD2 + dir * 512 + j0 + lr * 2) = hr;
            }
        }

        // barrier: arrive
        __syncthreads();
        if (tid == 0) {
            __threadfence();
            s_gen = atomicAdd(&g_bgen2[dir], 0u);
            if (atomicAdd(&g_bcnt2[dir], 1u) == 63u) {
                atomicExch(&g_bcnt2[dir], 0u);
                __threadfence();
                atomicAdd(&g_bgen2[dir], 1u);
            }
        }

        // prefetch xproj for t+1 (independent of barrier)
        if (t + 1 < TT) {
#pragma unroll
            for (int bb = 0; bb < 2; bb++) {
                const float* xr = xp + ((size_t)(w16 + lq + bb * 8) * TT + (t + 1)) * GG + j0 + lr * 2;
                xg2[bb][0] = *(const float2*)(xr);
                xg2[bb][1] = *(const float2*)(xr + 512);
                xg2[bb][2] = *(const float2*)(xr + 1024);
                xg2[bb][3] = *(const float2*)(xr + 1536);
            }
        }

        // barrier: wait
        if (tid == 0) {
            unsigned gv = s_gen;
            while (atomicAdd(&g_bgen2[dir], 0u) == gv) { __nanosleep(20); }
        }
        __syncthreads();
    }
}

// ---------------- tail kernels ----------------
__global__ void scores_k(const float* __restrict__ th, const float* __restrict__ aw2,
                         const float* __restrict__ ab2, float* __restrict__ sc)
{
    int r = blockIdx.x;
    const float* row = th + (size_t)r * HD2;
    float s = 0.f;
    for (int k = threadIdx.x; k < HD2; k += 128) s += row[k] * aw2[k];
    __shared__ float red[128];
    red[threadIdx.x] = s; __syncthreads();
    for (int o = 64; o > 0; o >>= 1) {
        if (threadIdx.x < o) red[threadIdx.x] += red[threadIdx.x + o];
        __syncthreads();
    }
    if (threadIdx.x == 0) sc[r] = red[0] + ab2[0];
}

__global__ void softmax_k(const float* __restrict__ sc, float* __restrict__ attw,
                          float* __restrict__ out_attw)
{
    int b = blockIdx.x, t = threadIdx.x;
    float v = sc[b * TT + t];
    __shared__ float red[TT];
    red[t] = v; __syncthreads();
    for (int o = 128; o > 0; o >>= 1) {
        if (t < o) red[t] = fmaxf(red[t], red[t + o]);
        __syncthreads();
    }
    float mx = red[0]; __syncthreads();
    float e = __expf(v - mx);
    red[t] = e; __syncthreads();
    for (int o = 128; o > 0; o >>= 1) {
        if (t < o) red[t] += red[t + o];
        __syncthreads();
    }
    float w = e / red[0];
    attw[b * TT + t] = w;
    if (out_attw) out_attw[b * TT + t] = w;
}

__global__ void context_k(const float* __restrict__ attw, const float* __restrict__ lo,
                          float* __restrict__ ctx)
{
    int b = blockIdx.y;
    int n = blockIdx.x * 256 + threadIdx.x;
    __shared__ float aw[TT];
    aw[threadIdx.x] = attw[b * TT + threadIdx.x];
    __syncthreads();
    float s = 0.f;
    const float* base = lo + (size_t)b * TT * HD2 + n;
#pragma unroll 4
    for (int t = 0; t < TT; t++) s += aw[t] * base[(size_t)t * HD2];
    ctx[b * HD2 + n] = s;
}

__global__ void cls1_k(const float* __restrict__ ctx, const float* __restrict__ w,
                       const float* __restrict__ bias, float* __restrict__ hc)
{
    int b = blockIdx.x, j = threadIdx.x;
    __shared__ float xs[HD2];
    xs[j] = ctx[b * HD2 + j];
    xs[j + 512] = ctx[b * HD2 + j + 512];
    __syncthreads();
    float s = bias[j];
    for (int k = 0; k < HD2; k++) s += xs[k] * w[k * HH + j];
    hc[b * HH + j] = fmaxf(s, 0.f);
}

__global__ void cls2_k(const float* __restrict__ hc, const float* __restrict__ w,
                       const float* __restrict__ bias, float* __restrict__ out)
{
    int b = blockIdx.x, j = threadIdx.x;
    __shared__ float xs[HH];
    for (int k = j; k < HH; k += 128) xs[k] = hc[b * HH + k];
    __syncthreads();
    if (j < NC) {
        float s = bias[j];
        for (int k = 0; k < HH; k++) s += xs[k] * w[k * NC + j];
        out[b * NC + j] = s;
    }
}

// ---------------- launch ----------------
extern "C" void kernel_launch(void* const* d_in, const int* in_sizes, int n_in,
                              void* d_out, int out_size)
{
    const float* x     = (const float*)d_in[0];
    const float* wih0f = (const float*)d_in[1];
    const float* whh0f = (const float*)d_in[2];
    const float* b0f   = (const float*)d_in[3];
    const float* wih0b = (const float*)d_in[4];
    const float* whh0b = (const float*)d_in[5];
    const float* b0b   = (const float*)d_in[6];
    const float* wih1f = (const float*)d_in[7];
    const float* whh1f = (const float*)d_in[8];
    const float* b1f   = (const float*)d_in[9];
    const float* wih1b = (const float*)d_in[10];
    const float* whh1b = (const float*)d_in[11];
    const float* b1b   = (const float*)d_in[12];
    const float* aw1   = (const float*)d_in[13];
    const float* ab1   = (const float*)d_in[14];
    const float* aw2   = (const float*)d_in[15];
    const float* ab2   = (const float*)d_in[16];
    const float* cw1   = (const float*)d_in[17];
    const float* cb1   = (const float*)d_in[18];
    const float* cw2   = (const float*)d_in[19];
    const float* cb2   = (const float*)d_in[20];
    float* out = (float*)d_out;

    float *xpf, *xpb, *h0, *lo, *lor, *awt, *xr, *w0f, *w0b, *w1f, *w1b, *sc, *aw, *ctx, *hc;
    cudaGetSymbolAddress((void**)&xpf, g_xpf);
    cudaGetSymbolAddress((void**)&xpb, g_xpb);
    cudaGetSymbolAddress((void**)&h0,  g_h0buf);
    cudaGetSymbolAddress((void**)&lo,  g_outbuf);
    cudaGetSymbolAddress((void**)&lor, g_lor);
    cudaGetSymbolAddress((void**)&awt, g_awt);
    cudaGetSymbolAddress((void**)&xr,  g_xr);
    cudaGetSymbolAddress((void**)&w0f, g_w0f);
    cudaGetSymbolAddress((void**)&w0b, g_w0b);
    cudaGetSymbolAddress((void**)&w1f, g_w1f);
    cudaGetSymbolAddress((void**)&w1b, g_w1b);
    cudaGetSymbolAddress((void**)&sc,  g_scoresb);
    cudaGetSymbolAddress((void**)&aw,  g_attwb);
    cudaGetSymbolAddress((void**)&ctx, g_ctx);
    cudaGetSymbolAddress((void**)&hc,  g_hc);

    cudaFuncSetAttribute(gemm_mma<0, 0>, cudaFuncAttributeMaxDynamicSharedMemorySize, GSMEM);
    cudaFuncSetAttribute(gemm_mma<1, 0>, cudaFuncAttributeMaxDynamicSharedMemorySize, GSMEM);
    cudaFuncSetAttribute(gemm_mma<0, 1>, cudaFuncAttributeMaxDynamicSharedMemorySize, GSMEM);
    cudaFuncSetAttribute(lstm_mma, cudaFuncAttributeMaxDynamicSharedMemorySize, SMEM_LSTM);

    // rounding passes
    round_k<<<1024, 256>>>((const float4*)x,     (float4*)xr,  BT * INN / 4);
    round_k<<<512, 256>>>((const float4*)wih0f, (float4*)w0f, GG * INN / 4);
    round_k<<<512, 256>>>((const float4*)wih0b, (float4*)w0b, GG * INN / 4);
    round_k<<<512, 256>>>((const float4*)wih1f, (float4*)w1f, GG * HD2 / 4);
    round_k<<<512, 256>>>((const float4*)wih1b, (float4*)w1b, GG * HD2 / 4);
    transpose_k<<<dim3(HD2 / 32, HD2 / 32), dim3(32, 32)>>>(aw1, awt, HD2, HD2);

    dim3 blk(256);
    dim3 gp(GG / 128, BT / 128);      // 16 x 256

    gemm_mma<0, 0><<<gp, blk, GSMEM>>>(xr, w0f, b0f, xpf, BT, GG, INN);
    gemm_mma<1, 0><<<gp, blk, GSMEM>>>(xr, w0b, b0b, xpb, BT, GG, INN);
    lstm_mma<<<128, 256, SMEM_LSTM>>>(xpf, xpb, whh0f, whh0b, h0, nullptr, 1);

    gemm_mma<0, 0><<<gp, blk, GSMEM>>>(h0, w1f, b1f, xpf, BT, GG, HD2);
    gemm_mma<1, 0><<<gp, blk, GSMEM>>>(h0, w1b, b1b, xpb, BT, GG, HD2);
    lstm_mma<<<128, 256, SMEM_LSTM>>>(xpf, xpb, whh1f, whh1b, lo, lor, 0);

    dim3 ga(HD2 / 128, BT / 128);     // 8 x 256
    gemm_mma<0, 1><<<ga, blk, GSMEM>>>(lor, awt, ab1, xpf, BT, HD2, HD2);
    scores_k<<<BT, 128>>>(xpf, aw2, ab2, sc);

    float* out_attw = (out_size >= (BB * NC + BT)) ? (out + BB * NC) : nullptr;
    softmax_k<<<BB, TT>>>(sc, aw, out_attw);
    context_k<<<dim3(HD2 / 256, BB), 256>>>(aw, lo, ctx);
    cls1_k<<<BB, 512>>>(ctx, cw1, cb1, hc);
    cls2_k<<<BB, 128>>>(hc, cw2, cb2, out);
}

// round 11
// speedup vs baseline: 1.2518x; 1.0179x over previous
#include <cuda_runtime.h>
#include <cuda_bf16.h>
#include <cstdint>

// Problem dims
#define BB   128
#define TT   256
#define HH   512
#define GG   2048
#define INN  1662
#define HD2  1024
#define NC   100
#define BT   32768

// ---------------- device scratch ----------------
__device__ float g_xpf[BT * GG];
__device__ float g_xpb[BT * GG];
__device__ float g_h0buf[BT * HD2];       // layer0 h (tf32-rounded)
__device__ float g_outbuf[BT * HD2];      // lstm_out fp32
__device__ float g_lor[BT * HD2];         // lstm_out tf32-rounded
__device__ float g_awt[HD2 * HD2];
__device__ float g_xr[BT * INN];
__device__ float g_w0f[GG * INN];
__device__ float g_w0b[GG * INN];
__device__ float g_w1f[GG * HD2];
__device__ float g_w1b[GG * HD2];
__device__ float g_hping[4 * BB * HH];
__device__ float g_scoresb[BT];
__device__ float g_attwb[BT];
__device__ float g_ctx[BB * HD2];
__device__ float g_hc[BB * HH];

__device__ unsigned g_bcnt2[2] = {0, 0};
__device__ unsigned g_bgen2[2] = {0, 0};

__device__ __forceinline__ uint32_t f2tf32(float x) {
    uint32_t u;
    asm("cvt.rna.tf32.f32 %0, %1;" : "=r"(u) : "f"(x));
    return u;
}

__device__ __forceinline__ void mma_tf32(float* d, const uint32_t* a, const uint32_t* b) {
    asm volatile(
        "mma.sync.aligned.m16n8k8.row.col.f32.tf32.tf32.f32 "
        "{%0,%1,%2,%3}, {%4,%5,%6,%7}, {%8,%9}, {%0,%1,%2,%3};"
        : "+f"(d[0]), "+f"(d[1]), "+f"(d[2]), "+f"(d[3])
        : "r"(a[0]), "r"(a[1]), "r"(a[2]), "r"(a[3]), "r"(b[0]), "r"(b[1]));
}

__device__ __forceinline__ void mma_bf16(float* d, const uint32_t* a, const uint32_t* b) {
    asm volatile(
        "mma.sync.aligned.m16n8k16.row.col.f32.bf16.bf16.f32 "
        "{%0,%1,%2,%3}, {%4,%5,%6,%7}, {%8,%9}, {%0,%1,%2,%3};"
        : "+f"(d[0]), "+f"(d[1]), "+f"(d[2]), "+f"(d[3])
        : "r"(a[0]), "r"(a[1]), "r"(a[2]), "r"(a[3]), "r"(b[0]), "r"(b[1]));
}

__device__ __forceinline__ uint32_t smem_u32(const void* p) {
    uint32_t a;
    asm("{ .reg .u64 t; cvta.to.shared.u64 t, %1; cvt.u32.u64 %0, t; }" : "=r"(a) : "l"(p));
    return a;
}
__device__ __forceinline__ void cp_async16(uint32_t dst, const void* src, int src_bytes) {
    asm volatile("cp.async.cg.shared.global [%0], [%1], 16, %2;"
                 :: "r"(dst), "l"(src), "r"(src_bytes) : "memory");
}
__device__ __forceinline__ void cp_async8(uint32_t dst, const void* src, int src_bytes) {
    asm volatile("cp.async.ca.shared.global [%0], [%1], 8, %2;"
                 :: "r"(dst), "l"(src), "r"(src_bytes) : "memory");
}
__device__ __forceinline__ void cp_commit() {
    asm volatile("cp.async.commit_group;" ::: "memory");
}
__device__ __forceinline__ void cp_wait0() {
    asm volatile("cp.async.wait_group 0;" ::: "memory");
}

// split a float2 (k0,k1) into packed bf16x2 hi and residual-lo registers
__device__ __forceinline__ void split_bf16x2(float2 p, uint32_t& hi, uint32_t& lo) {
    __nv_bfloat162 h2 = __floats2bfloat162_rn(p.x, p.y);
    uint32_t hu; memcpy(&hu, &h2, 4);
    float f0 = __uint_as_float(hu << 16);
    float f1 = __uint_as_float(hu & 0xFFFF0000u);
    __nv_bfloat162 l2 = __floats2bfloat162_rn(p.x - f0, p.y - f1);
    uint32_t lu; memcpy(&lu, &l2, 4);
    hi = hu; lo = lu;
}

// ---------------- rounding pass ----------------
__global__ void round_k(const float4* __restrict__ src, float4* __restrict__ dst, int n4)
{
    int stride = gridDim.x * blockDim.x;
    for (int i = blockIdx.x * blockDim.x + threadIdx.x; i < n4; i += stride) {
        float4 v = src[i];
        v.x = __uint_as_float(f2tf32(v.x));
        v.y = __uint_as_float(f2tf32(v.y));
        v.z = __uint_as_float(f2tf32(v.z));
        v.w = __uint_as_float(f2tf32(v.w));
        dst[i] = v;
    }
}

// ---------------- tf32 GEMM: chunk32, cp.async double-buffered, L2 group swizzle ----------
// 1D grid over MT*NT tiles; consecutive ~NT*18 CTAs cover all n-tiles of an
// 18-m-tile band so A (15MB) + W (14MB) stay L2-resident within one wave.
#define SSTR 36
#define GSMEM (2 * 2 * 128 * SSTR * 4)
#define GRPM 18

template<int FLIP, int ACT>
__global__ __launch_bounds__(256, 2)
void gemm_mma(const float* __restrict__ A, const float* __restrict__ W,
              const float* __restrict__ bias, float* __restrict__ C,
              int M, int N, int K)
{
    extern __shared__ float dsm[];
    float* sA = dsm;
    float* sB = dsm + 2 * 128 * SSTR;

    const int tid  = threadIdx.x;
    const int wid  = tid >> 5;
    const int lane = tid & 31;
    const int wm   = wid & 1;
    const int wn   = wid >> 1;

    // group swizzle: bid -> (mt, nt)
    const int NT = N >> 7;
    const int MT = M >> 7;
    int bid = blockIdx.x;
    int per_group = NT * GRPM;
    int grp  = bid / per_group;
    int rem  = bid - grp * per_group;
    int gm0  = grp * GRPM;
    int rows = MT - gm0; if (rows > GRPM) rows = GRPM;
    const int m0 = (gm0 + (rem % rows)) * 128;
    const int n0 = (rem / rows) * 128;

    const int lq = lane >> 2;
    const int lr = lane & 3;

    const uint32_t sA_base = smem_u32(sA);
    const uint32_t sB_base = smem_u32(sB);
    const bool use16 = ((K & 3) == 0);

    float acc[4][4][4];
#pragma unroll
    for (int i = 0; i < 4; i++)
#pragma unroll
        for (int j = 0; j < 4; j++)
#pragma unroll
            for (int r = 0; r < 4; r++) acc[i][j][r] = 0.f;

    const int nk = (K + 31) / 32;

    auto arow_of = [&](int r) {
        int gm = m0 + r;
        if (FLIP) { int bI = gm >> 8; int t = gm & 255; return (bI << 8) + (255 - t); }
        return gm;
    };

    auto load_chunk16 = [&](int kc, int buf) {
        const int k0 = kc * 32;
        const uint32_t boff = (uint32_t)buf * 128 * SSTR * 4;
#pragma unroll
        for (int i = 0; i < 4; i++) {
            int s  = tid + i * 256;
            int r  = s >> 3;
            int c4 = s & 7;
            int k  = k0 + c4 * 4;
            int nbf = K - k; nbf = nbf < 0 ? 0 : (nbf > 4 ? 4 : nbf);
            int bytes = nbf * 4;
            int ksrc = (k < K) ? k : 0;
            uint32_t soff = (uint32_t)(r * SSTR + c4 * 4) * 4;
            cp_async16(sA_base + boff + soff, A + (size_t)arow_of(r) * K + ksrc, bytes);
            cp_async16(sB_base + boff + soff, W + (size_t)(n0 + r) * K + ksrc, bytes);
        }
        cp_commit();
    };

    auto load_chunk8 = [&](int kc, int buf) {
        const int k0 = kc * 32;
        const uint32_t boff = (uint32_t)buf * 128 * SSTR * 4;
#pragma unroll
        for (int i = 0; i < 8; i++) {
            int s  = tid + i * 256;
            int r  = s >> 4;
            int c2 = s & 15;
            int k  = k0 + c2 * 2;
            int nbf = K - k; nbf = nbf < 0 ? 0 : (nbf > 2 ? 2 : nbf);
            int bytes = nbf * 4;
            int ksrc = (k < K) ? k : 0;
            uint32_t soff = (uint32_t)(r * SSTR + c2 * 2) * 4;
            cp_async8(sA_base + boff + soff, A + (size_t)arow_of(r) * K + ksrc, bytes);
            cp_async8(sB_base + boff + soff, W + (size_t)(n0 + r) * K + ksrc, bytes);
        }
        cp_commit();
    };

    auto load_chunk = [&](int kc, int buf) {
        if (use16) load_chunk16(kc, buf); else load_chunk8(kc, buf);
    };

    load_chunk(0, 0);

    for (int kc = 0; kc < nk; kc++) {
        cp_wait0();
        __syncthreads();
        if (kc + 1 < nk) load_chunk(kc + 1, (kc + 1) & 1);

        const float* bA = sA + (kc & 1) * 128 * SSTR;
        const float* bB = sB + (kc & 1) * 128 * SSTR;
#pragma unroll
        for (int ks = 0; ks < 4; ks++) {
            const int kb = ks * 8 + lr;
            uint32_t af[4][4];
#pragma unroll
            for (int mt = 0; mt < 4; mt++) {
                int base = wm * 64 + mt * 16 + lq;
                af[mt][0] = __float_as_uint(bA[ base      * SSTR + kb]);
                af[mt][1] = __float_as_uint(bA[(base + 8) * SSTR + kb]);
                af[mt][2] = __float_as_uint(bA[ base      * SSTR + kb + 4]);
                af[mt][3] = __float_as_uint(bA[(base + 8) * SSTR + kb + 4]);
            }
            uint32_t bf[4][2];
#pragma unroll
            for (int nt = 0; nt < 4; nt++) {
                int brow = wn * 32 + nt * 8 + lq;
                bf[nt][0] = __float_as_uint(bB[brow * SSTR + kb]);
                bf[nt][1] = __float_as_uint(bB[brow * SSTR + kb + 4]);
            }
#pragma unroll
            for (int mt = 0; mt < 4; mt++)
#pragma unroll
                for (int nt = 0; nt < 4; nt++)
                    mma_tf32(acc[mt][nt], af[mt], bf[nt]);
        }
        __syncthreads();
    }

    const int rbase = m0 + wm * 64;
    const int cbase = n0 + wn * 32;
#pragma unroll
    for (int mt = 0; mt < 4; mt++) {
#pragma unroll
        for (int nt = 0; nt < 4; nt++) {
            int c  = cbase + nt * 8 + lr * 2;
            float b0v = bias[c], b1v = bias[c + 1];
            int r0 = rbase + mt * 16 + lq;
            float v0 = acc[mt][nt][0] + b0v;
            float v1 = acc[mt][nt][1] + b1v;
            float v2 = acc[mt][nt][2] + b0v;
            float v3 = acc[mt][nt][3] + b1v;
            if (ACT == 1) { v0 = tanhf(v0); v1 = tanhf(v1); v2 = tanhf(v2); v3 = tanhf(v3); }
            *(float2*)(C + (size_t)r0 * N + c)       = make_float2(v0, v1);
            *(float2*)(C + (size_t)(r0 + 8) * N + c) = make_float2(v2, v3);
        }
    }
}

// ---------------- weight transpose with tf32 rounding ----------------
__global__ void transpose_k(const float* __restrict__ src, float* __restrict__ dst, int R, int Cc)
{
    __shared__ float t[32][33];
    int r0 = blockIdx.y * 32, c0 = blockIdx.x * 32;
    t[threadIdx.y][threadIdx.x] = src[(size_t)(r0 + threadIdx.y) * Cc + c0 + threadIdx.x];
    __syncthreads();
    dst[(size_t)(c0 + threadIdx.y) * R + r0 + threadIdx.x] =
        __uint_as_float(f2tf32(t[threadIdx.x][threadIdx.y]));
}

// ---------------- persistent LSTM: bf16 hi/lo split (m16n8k16), cp.async h ----------------
#define WPLANE (8 * 32 * 104)
#define HSTRL 72
#define SMEM_LSTM (2 * WPLANE * 2 + 2 * 128 * HSTRL * 4)

__global__ __launch_bounds__(256, 1)
void lstm_mma(const float* __restrict__ xpF, const float* __restrict__ xpB,
              const float* __restrict__ whF, const float* __restrict__ whB,
              float* __restrict__ hout, float* __restrict__ houtr, int round_out)
{
    extern __shared__ char smemc[];
    __nv_bfloat16* sWhi = (__nv_bfloat16*)smemc;
    __nv_bfloat16* sWlo = sWhi + WPLANE;
    float* sH = (float*)(smemc + 2 * WPLANE * 2);
    __shared__ unsigned s_gen;

    const int tid  = threadIdx.x;
    const int bi   = blockIdx.x;
    const int w    = tid >> 5;
    const int lane = tid & 31;
    const int lq   = lane >> 2;
    const int lr   = lane & 3;
    const int dir  = bi >> 6;
    const int j0   = (bi & 63) * 8;
    const int w16  = w * 16;
    const float* wh = dir ? whB : whF;
    const float* xp = dir ? xpB : xpF;
    const uint32_t sH_base = smem_u32(sH);

    for (int e = tid; e < 32 * 512; e += 256) {
        int n = e >> 9, k = e & 511;
        int c = k >> 6, kin = k & 63;
        int grow = (n >> 3) * 512 + j0 + (n & 7);
        float v = wh[(size_t)grow * HH + k];
        __nv_bfloat16 hb = __float2bfloat16_rn(v);
        float hf = __bfloat162float(hb);
        __nv_bfloat16 lb = __float2bfloat16_rn(v - hf);
        int idx = (c * 32 + n) * 104 + kin;
        sWhi[idx] = hb;
        sWlo[idx] = lb;
    }
    __syncthreads();

    float creg[4] = {0.f, 0.f, 0.f, 0.f};

    float2 xg2[2][4];
#pragma unroll
    for (int bb = 0; bb < 2; bb++) {
        const float* xr = xp + ((size_t)(w16 + lq + bb * 8) * TT + 0) * GG + j0 + lr * 2;
        xg2[bb][0] = *(const float2*)(xr);
        xg2[bb][1] = *(const float2*)(xr + 512);
        xg2[bb][2] = *(const float2*)(xr + 1024);
        xg2[bb][3] = *(const float2*)(xr + 1536);
    }

    for (int t = 0; t < TT; t++) {
        float acc[4][4];
#pragma unroll
        for (int nt = 0; nt < 4; nt++)
#pragma unroll
            for (int r = 0; r < 4; r++) acc[nt][r] = 0.f;

        if (t > 0) {
            const float* hprev = g_hping + ((((t - 1) & 1) << 1) + dir) * (BB * HH);

            auto load_hchunk = [&](int kc, int buf) {
                const uint32_t boff = (uint32_t)buf * 128 * HSTRL * 4;
#pragma unroll
                for (int i = 0; i < 8; i++) {
                    int s   = tid + i * 256;
                    int row = s >> 4;
                    int c4  = s & 15;
                    cp_async16(sH_base + boff + (uint32_t)(row * HSTRL + c4 * 4) * 4,
                               hprev + row * 512 + kc * 64 + c4 * 4, 16);
                }
                cp_commit();
            };

            load_hchunk(0, 0);
            for (int kc = 0; kc < 8; kc++) {
                cp_wait0();
                __syncthreads();
                if (kc < 7) load_hchunk(kc + 1, (kc + 1) & 1);

                const float* bH = sH + (kc & 1) * 128 * HSTRL;
                const __nv_bfloat16* Wchi = sWhi + kc * 32 * 104;
                const __nv_bfloat16* Wclo = sWlo + kc * 32 * 104;
#pragma unroll
                for (int ks = 0; ks < 4; ks++) {
                    const int kk = ks * 16 + 2 * lr;
                    const float* hr0 = bH + (w16 + lq)     * HSTRL;
                    const float* hr1 = bH + (w16 + lq + 8) * HSTRL;
                    float2 p00 = *(const float2*)(hr0 + kk);
                    float2 p10 = *(const float2*)(hr1 + kk);
                    float2 p01 = *(const float2*)(hr0 + kk + 8);
                    float2 p11 = *(const float2*)(hr1 + kk + 8);
                    uint32_t ahi[4], alo[4];
                    split_bf16x2(p00, ahi[0], alo[0]);
                    split_bf16x2(p10, ahi[1], alo[1]);
                    split_bf16x2(p01, ahi[2], alo[2]);
                    split_bf16x2(p11, ahi[3], alo[3]);
#pragma unroll
                    for (int nt = 0; nt < 4; nt++) {
                        const __nv_bfloat16* wr_hi = Wchi + (nt * 8 + lq) * 104 + kk;
                        const __nv_bfloat16* wr_lo = Wclo + (nt * 8 + lq) * 104 + kk;
                        uint32_t bhi[2], blo[2];
                        bhi[0] = *(const uint32_t*)(wr_hi);
                        bhi[1] = *(const uint32_t*)(wr_hi + 8);
                        blo[0] = *(const uint32_t*)(wr_lo);
                        blo[1] = *(const uint32_t*)(wr_lo + 8);
                        mma_bf16(acc[nt], ahi, bhi);
                        mma_bf16(acc[nt], alo, bhi);
                        mma_bf16(acc[nt], ahi, blo);
                    }
                }
                __syncthreads();
            }
        }

        const int tt = dir ? (TT - 1 - t) : t;
        float* hnext = g_hping + (((t & 1) << 1) + dir) * (BB * HH);
#pragma unroll
        for (int bb = 0; bb < 2; bb++) {
            int b = w16 + lq + bb * 8;
            int i0 = bb * 2;

            float zi = acc[0][i0] + xg2[bb][0].x, zf = acc[1][i0] + xg2[bb][1].x;
            float zg = acc[2][i0] + xg2[bb][2].x, zo = acc[3][i0] + xg2[bb][3].x;
            float si = 1.f / (1.f + __expf(-zi));
            float sf = 1.f / (1.f + __expf(-zf));
            float so = 1.f / (1.f + __expf(-zo));
            float tg = tanhf(zg);
            creg[i0] = sf * creg[i0] + si * tg;
            float h0v = so * tanhf(creg[i0]);

            zi = acc[0][i0 + 1] + xg2[bb][0].y; zf = acc[1][i0 + 1] + xg2[bb][1].y;
            zg = acc[2][i0 + 1] + xg2[bb][2].y; zo = acc[3][i0 + 1] + xg2[bb][3].y;
            si = 1.f / (1.f + __expf(-zi));
            sf = 1.f / (1.f + __expf(-zf));
            so = 1.f / (1.f + __expf(-zo));
            tg = tanhf(zg);
            creg[i0 + 1] = sf * creg[i0 + 1] + si * tg;
            float h1v = so * tanhf(creg[i0 + 1]);

            float2 hv = make_float2(h0v, h1v);
            *(float2*)(hnext + b * 512 + j0 + lr * 2) = hv;
            float2 ho = round_out
                ? make_float2(__uint_as_float(f2tf32(h0v)), __uint_as_float(f2tf32(h1v)))
                : hv;
            *(float2*)(hout + ((size_t)b * TT + tt) * HD2 + dir * 512 + j0 + lr * 2) = ho;
            if (houtr) {
                float2 hr = make_float2(__uint_as_float(f2tf32(h0v)), __uint_as_float(f2tf32(h1v)));
                *(float2*)(houtr + ((size_t)b * TT + tt) * HD2 + dir * 512 + j0 + lr * 2) = hr;
            }
        }

        // barrier: arrive
        __syncthreads();
        if (tid == 0) {
            __threadfence();
            s_gen = atomicAdd(&g_bgen2[dir], 0u);
            if (atomicAdd(&g_bcnt2[dir], 1u) == 63u) {
                atomicExch(&g_bcnt2[dir], 0u);
                __threadfence();
                atomicAdd(&g_bgen2[dir], 1u);
            }
        }

        // prefetch xproj for t+1
        if (t + 1 < TT) {
#pragma unroll
            for (int bb = 0; bb < 2; bb++) {
                const float* xr = xp + ((size_t)(w16 + lq + bb * 8) * TT + (t + 1)) * GG + j0 + lr * 2;
                xg2[bb][0] = *(const float2*)(xr);
                xg2[bb][1] = *(const float2*)(xr + 512);
                xg2[bb][2] = *(const float2*)(xr + 1024);
                xg2[bb][3] = *(const float2*)(xr + 1536);
            }
        }

        // barrier: wait
        if (tid == 0) {
            unsigned gv = s_gen;
            while (atomicAdd(&g_bgen2[dir], 0u) == gv) { __nanosleep(20); }
        }
        __syncthreads();
    }
}

// ---------------- tail kernels ----------------
__global__ void scores_k(const float* __restrict__ th, const float* __restrict__ aw2,
                         const float* __restrict__ ab2, float* __restrict__ sc)
{
    int r = blockIdx.x;
    const float* row = th + (size_t)r * HD2;
    float s = 0.f;
    for (int k = threadIdx.x; k < HD2; k += 128) s += row[k] * aw2[k];
    __shared__ float red[128];
    red[threadIdx.x] = s; __syncthreads();
    for (int o = 64; o > 0; o >>= 1) {
        if (threadIdx.x < o) red[threadIdx.x] += red[threadIdx.x + o];
        __syncthreads();
    }
    if (threadIdx.x == 0) sc[r] = red[0] + ab2[0];
}

__global__ void softmax_k(const float* __restrict__ sc, float* __restrict__ attw,
                          float* __restrict__ out_attw)
{
    int b = blockIdx.x, t = threadIdx.x;
    float v = sc[b * TT + t];
    __shared__ float red[TT];
    red[t] = v; __syncthreads();
    for (int o = 128; o > 0; o >>= 1) {
        if (t < o) red[t] = fmaxf(red[t], red[t + o]);
        __syncthreads();
    }
    float mx = red[0]; __syncthreads();
    float e = __expf(v - mx);
    red[t] = e; __syncthreads();
    for (int o = 128; o > 0; o >>= 1) {
        if (t < o) red[t] += red[t + o];
        __syncthreads();
    }
    float w = e / red[0];
    attw[b * TT + t] = w;
    if (out_attw) out_attw[b * TT + t] = w;
}

__global__ void context_k(const float* __restrict__ attw, const float* __restrict__ lo,
                          float* __restrict__ ctx)
{
    int b = blockIdx.y;
    int n = blockIdx.x * 256 + threadIdx.x;
    __shared__ float aw[TT];
    aw[threadIdx.x] = attw[b * TT + threadIdx.x];
    __syncthreads();
    float s = 0.f;
    const float* base = lo + (size_t)b * TT * HD2 + n;
#pragma unroll 4
    for (int t = 0; t < TT; t++) s += aw[t] * base[(size_t)t * HD2];
    ctx[b * HD2 + n] = s;
}

__global__ void cls1_k(const float* __restrict__ ctx, const float* __restrict__ w,
                       const float* __restrict__ bias, float* __restrict__ hc)
{
    int b = blockIdx.x, j = threadIdx.x;
    __shared__ float xs[HD2];
    xs[j] = ctx[b * HD2 + j];
    xs[j + 512] = ctx[b * HD2 + j + 512];
    __syncthreads();
    float s = bias[j];
    for (int k = 0; k < HD2; k++) s += xs[k] * w[k * HH + j];
    hc[b * HH + j] = fmaxf(s, 0.f);
}

__global__ void cls2_k(const float* __restrict__ hc, const float* __restrict__ w,
                       const float* __restrict__ bias, float* __restrict__ out)
{
    int b = blockIdx.x, j = threadIdx.x;
    __shared__ float xs[HH];
    for (int k = j; k < HH; k += 128) xs[k] = hc[b * HH + k];
    __syncthreads();
    if (j < NC) {
        float s = bias[j];
        for (int k = 0; k < HH; k++) s += xs[k] * w[k * NC + j];
        out[b * NC + j] = s;
    }
}

// ---------------- launch ----------------
extern "C" void kernel_launch(void* const* d_in, const int* in_sizes, int n_in,
                              void* d_out, int out_size)
{
    const float* x     = (const float*)d_in[0];
    const float* wih0f = (const float*)d_in[1];
    const float* whh0f = (const float*)d_in[2];
    const float* b0f   = (const float*)d_in[3];
    const float* wih0b = (const float*)d_in[4];
    const float* whh0b = (const float*)d_in[5];
    const float* b0b   = (const float*)d_in[6];
    const float* wih1f = (const float*)d_in[7];
    const float* whh1f = (const float*)d_in[8];
    const float* b1f   = (const float*)d_in[9];
    const float* wih1b = (const float*)d_in[10];
    const float* whh1b = (const float*)d_in[11];
    const float* b1b   = (const float*)d_in[12];
    const float* aw1   = (const float*)d_in[13];
    const float* ab1   = (const float*)d_in[14];
    const float* aw2   = (const float*)d_in[15];
    const float* ab2   = (const float*)d_in[16];
    const float* cw1   = (const float*)d_in[17];
    const float* cb1   = (const float*)d_in[18];
    const float* cw2   = (const float*)d_in[19];
    const float* cb2   = (const float*)d_in[20];
    float* out = (float*)d_out;

    float *xpf, *xpb, *h0, *lo, *lor, *awt, *xr, *w0f, *w0b, *w1f, *w1b, *sc, *aw, *ctx, *hc;
    cudaGetSymbolAddress((void**)&xpf, g_xpf);
    cudaGetSymbolAddress((void**)&xpb, g_xpb);
    cudaGetSymbolAddress((void**)&h0,  g_h0buf);
    cudaGetSymbolAddress((void**)&lo,  g_outbuf);
    cudaGetSymbolAddress((void**)&lor, g_lor);
    cudaGetSymbolAddress((void**)&awt, g_awt);
    cudaGetSymbolAddress((void**)&xr,  g_xr);
    cudaGetSymbolAddress((void**)&w0f, g_w0f);
    cudaGetSymbolAddress((void**)&w0b, g_w0b);
    cudaGetSymbolAddress((void**)&w1f, g_w1f);
    cudaGetSymbolAddress((void**)&w1b, g_w1b);
    cudaGetSymbolAddress((void**)&sc,  g_scoresb);
    cudaGetSymbolAddress((void**)&aw,  g_attwb);
    cudaGetSymbolAddress((void**)&ctx, g_ctx);
    cudaGetSymbolAddress((void**)&hc,  g_hc);

    cudaFuncSetAttribute(gemm_mma<0, 0>, cudaFuncAttributeMaxDynamicSharedMemorySize, GSMEM);
    cudaFuncSetAttribute(gemm_mma<1, 0>, cudaFuncAttributeMaxDynamicSharedMemorySize, GSMEM);
    cudaFuncSetAttribute(gemm_mma<0, 1>, cudaFuncAttributeMaxDynamicSharedMemorySize, GSMEM);
    cudaFuncSetAttribute(lstm_mma, cudaFuncAttributeMaxDynamicSharedMemorySize, SMEM_LSTM);

    // rounding passes
    round_k<<<1024, 256>>>((const float4*)x,     (float4*)xr,  BT * INN / 4);
    round_k<<<512, 256>>>((const float4*)wih0f, (float4*)w0f, GG * INN / 4);
    round_k<<<512, 256>>>((const float4*)wih0b, (float4*)w0b, GG * INN / 4);
    round_k<<<512, 256>>>((const float4*)wih1f, (float4*)w1f, GG * HD2 / 4);
    round_k<<<512, 256>>>((const float4*)wih1b, (float4*)w1b, GG * HD2 / 4);
    transpose_k<<<dim3(HD2 / 32, HD2 / 32), dim3(32, 32)>>>(aw1, awt, HD2, HD2);

    dim3 blk(256);
    const int TILES_P = (GG / 128) * (BT / 128);    // 4096
    const int TILES_A = (HD2 / 128) * (BT / 128);   // 2048

    gemm_mma<0, 0><<<TILES_P, blk, GSMEM>>>(xr, w0f, b0f, xpf, BT, GG, INN);
    gemm_mma<1, 0><<<TILES_P, blk, GSMEM>>>(xr, w0b, b0b, xpb, BT, GG, INN);
    lstm_mma<<<128, 256, SMEM_LSTM>>>(xpf, xpb, whh0f, whh0b, h0, nullptr, 1);

    gemm_mma<0, 0><<<TILES_P, blk, GSMEM>>>(h0, w1f, b1f, xpf, BT, GG, HD2);
    gemm_mma<1, 0><<<TILES_P, blk, GSMEM>>>(h0, w1b, b1b, xpb, BT, GG, HD2);
    lstm_mma<<<128, 256, SMEM_LSTM>>>(xpf, xpb, whh1f, whh1b, lo, lor, 0);

    gemm_mma<0, 1><<<TILES_A, blk, GSMEM>>>(lor, awt, ab1, xpf, BT, HD2, HD2);
    scores_k<<<BT, 128>>>(xpf, aw2, ab2, sc);

    float* out_attw = (out_size >= (BB * NC + BT)) ? (out + BB * NC) : nullptr;
    softmax_k<<<BB, TT>>>(sc, aw, out_attw);
    context_k<<<dim3(HD2 / 256, BB), 256>>>(aw, lo, ctx);
    cls1_k<<<BB, 512>>>(ctx, cw1, cb1, hc);
    cls2_k<<<BB, 128>>>(hc, cw2, cb2, out);
}